// round 17
// baseline (speedup 1.0000x reference)
#include <cuda_runtime.h>
#include <cuda_fp16.h>

#define THREADS 512
#define RPB     8
#define NCTA    128
#define SEQ     1024
#define GATES   512
#define HID     128

// ---- smem ----
#define B_STRIDE  80
#define B_BUF     2560
#define B_OFF     0         // double buffered
#define RED_OFF   5120
#define SMEM_TOTAL 9216

typedef unsigned int u32;

// f16-accumulator HMMA: D regs = {(rowg, col2q|2q+1), (rowg+8, col2q|2q+1)}
static __device__ __forceinline__ void mma_f16h(u32* d, const uint4& a, u32 b0, u32 b1) {
    asm volatile("mma.sync.aligned.m16n8k16.row.col.f16.f16.f16.f16 "
        "{%0,%1}, {%2,%3,%4,%5}, {%6,%7}, {%0,%1};"
        : "+r"(d[0]), "+r"(d[1])
        : "r"(a.x), "r"(a.y), "r"(a.z), "r"(a.w), "r"(b0), "r"(b1));
}
static __device__ __forceinline__ void mma_f32(float* d, const uint4& a, u32 b0, u32 b1) {
    asm volatile("mma.sync.aligned.m16n8k16.row.col.f32.f16.f16.f32 "
        "{%0,%1,%2,%3}, {%4,%5,%6,%7}, {%8,%9}, {%0,%1,%2,%3};"
        : "+f"(d[0]), "+f"(d[1]), "+f"(d[2]), "+f"(d[3])
        : "r"(a.x), "r"(a.y), "r"(a.z), "r"(a.w), "r"(b0), "r"(b1));
}
static __device__ __forceinline__ float tanhap(float x) {
    float r; asm("tanh.approx.f32 %0, %1;" : "=f"(r) : "f"(x)); return r;
}
static __device__ __forceinline__ u32 tanh2u(u32 v) {
    u32 r; asm("tanh.approx.f16x2 %0, %1;" : "=r"(r) : "r"(v)); return r;
}
static __device__ __forceinline__ u32 packf2(float lo, float hi) {   // lo -> low half
    u32 r; asm("cvt.rn.f16x2.f32 %0, %1, %2;" : "=r"(r) : "f"(hi), "f"(lo)); return r;
}
static __device__ __forceinline__ u32 pack_h2(float a, float b) {
    __half2 h = __halves2half2(__float2half_rn(a), __float2half_rn(b));
    return *reinterpret_cast<u32*>(&h);
}
static __device__ __forceinline__ __half2 asH2(u32 v) { return *reinterpret_cast<__half2*>(&v); }
static __device__ __forceinline__ u32 asU32(__half2 v) { return *reinterpret_cast<u32*>(&v); }

__global__ void __launch_bounds__(THREADS, 1)
lstm_c8_kernel(const float* __restrict__ x,  const float* __restrict__ Wi,
               const float* __restrict__ Wh, const float* __restrict__ b,
               const float* __restrict__ Wd, const float* __restrict__ bd,
               float* __restrict__ out)
{
    extern __shared__ char smem[];
    const int tid  = threadIdx.x;
    const int w    = tid >> 5;           // warp 0..15: hid set 8w..8w+7
    const int lane = tid & 31;
    const int g    = lane >> 2;          // hid p = 8w+g
    const int q    = lane & 3;           // batch cols 2q, 2q+1
    const int r0   = blockIdx.x * RPB;
    const int p    = 8 * w + g;

    // m-tiles: mt0 = i (x0.5) | g (x1) ; mt1 = f (x0.5) | o (x0.5)
    const int jI = p, jG = 256 + p, jF = 128 + p, jO = 384 + p;

    // ---- A = Wh^T fp16 fragments -> registers ----
    uint4 areg[2][8];
#pragma unroll
    for (int kt = 0; kt < 8; kt++) {
        int c0 = kt * 16 + 2 * q, c2 = c0 + 8;
        areg[0][kt].x = pack_h2(0.5f * Wh[c0 * GATES + jI], 0.5f * Wh[(c0 + 1) * GATES + jI]);
        areg[0][kt].y = pack_h2(Wh[c0 * GATES + jG],        Wh[(c0 + 1) * GATES + jG]);
        areg[0][kt].z = pack_h2(0.5f * Wh[c2 * GATES + jI], 0.5f * Wh[(c2 + 1) * GATES + jI]);
        areg[0][kt].w = pack_h2(Wh[c2 * GATES + jG],        Wh[(c2 + 1) * GATES + jG]);
        areg[1][kt].x = pack_h2(0.5f * Wh[c0 * GATES + jF], 0.5f * Wh[(c0 + 1) * GATES + jF]);
        areg[1][kt].y = pack_h2(0.5f * Wh[c0 * GATES + jO], 0.5f * Wh[(c0 + 1) * GATES + jO]);
        areg[1][kt].z = pack_h2(0.5f * Wh[c2 * GATES + jF], 0.5f * Wh[(c2 + 1) * GATES + jF]);
        areg[1][kt].w = pack_h2(0.5f * Wh[c2 * GATES + jO], 0.5f * Wh[(c2 + 1) * GATES + jO]);
    }
    // half2 constants (sigmoid gates pre-scaled 0.5; g unscaled)
    const u32 biasI2 = pack_h2(0.5f * b[jI], 0.5f * b[jI]);
    const u32 biasG2 = pack_h2(b[jG], b[jG]);
    const u32 biasF2 = pack_h2(0.5f * b[jF], 0.5f * b[jF]);
    const u32 biasO2 = pack_h2(0.5f * b[jO], 0.5f * b[jO]);
    const __half2 wiI2 = asH2(pack_h2(0.5f * Wi[jI], 0.5f * Wi[jI]));
    const __half2 wiG2 = asH2(pack_h2(Wi[jG], Wi[jG]));
    const __half2 wiF2 = asH2(pack_h2(0.5f * Wi[jF], 0.5f * Wi[jF]));
    const __half2 wiO2 = asH2(pack_h2(0.5f * Wi[jO], 0.5f * Wi[jO]));
    const __half2 h05  = asH2(pack_h2(0.5f, 0.5f));

    // B-frag writer offsets (verified layout)
    const int off0 = ((2 * q) * 4 + ((p & 7) >> 1)) * B_STRIDE
                   + (p >> 4) * 8 + (((p & 15) >= 8) ? 4 : 0) + (p & 1) * 2;
    const int off1 = off0 + 4 * B_STRIDE;

    for (int i = tid; i < (2 * B_BUF) / 4; i += THREADS)
        *reinterpret_cast<u32*>(smem + B_OFF + i * 4) = 0;

    const float* xr = x + (r0 + 2 * q) * SEQ;    // row 2q; row 2q+1 at +SEQ
    float x0c = xr[0], x1c = xr[SEQ];

    float c0s = 0.f, c1s = 0.f;
    float h0f = 0.f, h1f = 0.f;

    __syncthreads();

    // ============ steps 0..1022: f16 accum, 8 independent chains ============
#pragma unroll 2
    for (int s = 0; s < SEQ - 1; s++) {
        float x0n = xr[s + 1], x1n = xr[SEQ + s + 1];

        const char* Bc = smem + B_OFF + (s & 1) * B_BUF + lane * B_STRIDE;
        uint4 bv0 = *reinterpret_cast<const uint4*>(Bc);
        uint4 bv1 = *reinterpret_cast<const uint4*>(Bc + 16);
        uint4 bv2 = *reinterpret_cast<const uint4*>(Bc + 32);
        uint4 bv3 = *reinterpret_cast<const uint4*>(Bc + 48);

        // 8 independent chains: 4 per m-tile (RAW reuse distance = 8 issues)
        u32 x2 = packf2(x0c, x1c);
        u32 dA[4][2], dB[4][2];
        dA[0][0] = biasI2; dA[0][1] = biasG2;
        dB[0][0] = biasF2; dB[0][1] = biasO2;
        dA[1][0] = asU32(__hmul2(asH2(x2), wiI2));
        dA[1][1] = asU32(__hmul2(asH2(x2), wiG2));
        dB[1][0] = asU32(__hmul2(asH2(x2), wiF2));
        dB[1][1] = asU32(__hmul2(asH2(x2), wiO2));
        dA[2][0] = 0u; dA[2][1] = 0u; dB[2][0] = 0u; dB[2][1] = 0u;
        dA[3][0] = 0u; dA[3][1] = 0u; dB[3][0] = 0u; dB[3][1] = 0u;

        mma_f16h(dA[0], areg[0][0], bv0.x, bv0.y);
        mma_f16h(dB[0], areg[1][0], bv0.x, bv0.y);
        mma_f16h(dA[1], areg[0][1], bv0.z, bv0.w);
        mma_f16h(dB[1], areg[1][1], bv0.z, bv0.w);
        mma_f16h(dA[2], areg[0][2], bv1.x, bv1.y);
        mma_f16h(dB[2], areg[1][2], bv1.x, bv1.y);
        mma_f16h(dA[3], areg[0][3], bv1.z, bv1.w);
        mma_f16h(dB[3], areg[1][3], bv1.z, bv1.w);
        mma_f16h(dA[0], areg[0][4], bv2.x, bv2.y);
        mma_f16h(dB[0], areg[1][4], bv2.x, bv2.y);
        mma_f16h(dA[1], areg[0][5], bv2.z, bv2.w);
        mma_f16h(dB[1], areg[1][5], bv2.z, bv2.w);
        mma_f16h(dA[2], areg[0][6], bv3.x, bv3.y);
        mma_f16h(dB[2], areg[1][6], bv3.x, bv3.y);
        mma_f16h(dA[3], areg[0][7], bv3.z, bv3.w);
        mma_f16h(dB[3], areg[1][7], bv3.z, bv3.w);

        // ---- merge chains (12 HADD2) ----
        __half2 vi = __hadd2(__hadd2(asH2(dA[0][0]), asH2(dA[1][0])),
                             __hadd2(asH2(dA[2][0]), asH2(dA[3][0])));
        __half2 vg = __hadd2(__hadd2(asH2(dA[0][1]), asH2(dA[1][1])),
                             __hadd2(asH2(dA[2][1]), asH2(dA[3][1])));
        __half2 vf = __hadd2(__hadd2(asH2(dB[0][0]), asH2(dB[1][0])),
                             __hadd2(asH2(dB[2][0]), asH2(dB[3][0])));
        __half2 vo = __hadd2(__hadd2(asH2(dB[0][1]), asH2(dB[1][1])),
                             __hadd2(asH2(dB[2][1]), asH2(dB[3][1])));

        // ---- f16x2 activations ----
        __half2 i2 = __hfma2(asH2(tanh2u(asU32(vi))), h05, h05);
        __half2 g2 = asH2(tanh2u(asU32(vg)));
        __half2 f2 = __hfma2(asH2(tanh2u(asU32(vf))), h05, h05);
        __half2 o2 = __hfma2(asH2(tanh2u(asU32(vo))), h05, h05);

        // ---- update: c in fp32 ----
        __half2 ig2 = __hmul2(i2, g2);
        c0s = fmaf(__low2float(f2),  c0s, __low2float(ig2));
        c1s = fmaf(__high2float(f2), c1s, __high2float(ig2));
        __half2 tc = asH2(tanh2u(packf2(c0s, c1s)));
        __half2 h2v = __hmul2(o2, tc);

        char* Bn = smem + B_OFF + ((s + 1) & 1) * B_BUF;
        *reinterpret_cast<unsigned short*>(Bn + off0) = __half_as_ushort(__low2half(h2v));
        *reinterpret_cast<unsigned short*>(Bn + off1) = __half_as_ushort(__high2half(h2v));

        x0c = x0n; x1c = x1n;

        __syncthreads();   // B[nxt] published; B[cur] reads complete
    }

    // ============ peeled final step: full f32 accum + scalar f32 act ============
    {
        const int s = SEQ - 1;
        const char* Bc = smem + B_OFF + (s & 1) * B_BUF + lane * B_STRIDE;
        uint4 bv0 = *reinterpret_cast<const uint4*>(Bc);
        uint4 bv1 = *reinterpret_cast<const uint4*>(Bc + 16);
        uint4 bv2 = *reinterpret_cast<const uint4*>(Bc + 32);
        uint4 bv3 = *reinterpret_cast<const uint4*>(Bc + 48);

        const float bIf = 0.5f * b[jI], bGf = b[jG], bFf = 0.5f * b[jF], bOf = 0.5f * b[jO];
        const float wIf = 0.5f * Wi[jI], wGf = Wi[jG], wFf = 0.5f * Wi[jF], wOf = 0.5f * Wi[jO];

        float dA[4] = { fmaf(x0c, wIf, bIf), fmaf(x1c, wIf, bIf),
                        fmaf(x0c, wGf, bGf), fmaf(x1c, wGf, bGf) };
        float dB[4] = { fmaf(x0c, wFf, bFf), fmaf(x1c, wFf, bFf),
                        fmaf(x0c, wOf, bOf), fmaf(x1c, wOf, bOf) };
        mma_f32(dA, areg[0][0], bv0.x, bv0.y);
        mma_f32(dB, areg[1][0], bv0.x, bv0.y);
        mma_f32(dA, areg[0][1], bv0.z, bv0.w);
        mma_f32(dB, areg[1][1], bv0.z, bv0.w);
        mma_f32(dA, areg[0][2], bv1.x, bv1.y);
        mma_f32(dB, areg[1][2], bv1.x, bv1.y);
        mma_f32(dA, areg[0][3], bv1.z, bv1.w);
        mma_f32(dB, areg[1][3], bv1.z, bv1.w);
        mma_f32(dA, areg[0][4], bv2.x, bv2.y);
        mma_f32(dB, areg[1][4], bv2.x, bv2.y);
        mma_f32(dA, areg[0][5], bv2.z, bv2.w);
        mma_f32(dB, areg[1][5], bv2.z, bv2.w);
        mma_f32(dA, areg[0][6], bv3.x, bv3.y);
        mma_f32(dB, areg[1][6], bv3.x, bv3.y);
        mma_f32(dA, areg[0][7], bv3.z, bv3.w);
        mma_f32(dB, areg[1][7], bv3.z, bv3.w);

        // D layout (f32): {row g: col2q, col2q+1, row g+8: col2q, col2q+1}
        float tI0 = tanhap(dA[0]);
        float tI1 = tanhap(dA[1]);
        float tG0 = tanhap(dA[2]);
        float tG1 = tanhap(dA[3]);
        float tF0 = tanhap(dB[0]);
        float tF1 = tanhap(dB[1]);
        float o0  = fmaf(0.5f, tanhap(dB[2]), 0.5f);
        float o1  = fmaf(0.5f, tanhap(dB[3]), 0.5f);

        float P0 = fmaf(tI0, tG0, tG0);          // 2*i*g
        float P1 = fmaf(tI1, tG1, tG1);
        float Q0 = fmaf(tF0, c0s, c0s);          // 2*f*c
        float Q1 = fmaf(tF1, c1s, c1s);
        c0s = 0.5f * (P0 + Q0);
        c1s = 0.5f * (P1 + Q1);

        h0f = o0 * tanhap(c0s);
        h1f = o1 * tanhap(c1s);
    }

    // ============ output: out[r] = h . Wd + bd ============
    float* red = reinterpret_cast<float*>(smem + RED_OFF);
    {
        float wd = Wd[p];
        red[p * 8 + 2 * q]     = h0f * wd;
        red[p * 8 + 2 * q + 1] = h1f * wd;
    }
    __syncthreads();
    if (tid < RPB) {
        float sum = 0.f;
        for (int pp = 0; pp < HID; pp++) sum += red[pp * 8 + tid];
        out[r0 + tid] = sum + bd[0];
    }
}

extern "C" void kernel_launch(void* const* d_in, const int* in_sizes, int n_in,
                              void* d_out, int out_size)
{
    (void)in_sizes; (void)n_in; (void)out_size;
    const float* x  = (const float*)d_in[0];
    const float* Wi = (const float*)d_in[1];
    const float* Wh = (const float*)d_in[2];
    const float* b  = (const float*)d_in[3];
    const float* Wd = (const float*)d_in[4];
    const float* bd = (const float*)d_in[5];
    float* out = (float*)d_out;

    cudaFuncSetAttribute(lstm_c8_kernel,
                         cudaFuncAttributeMaxDynamicSharedMemorySize, SMEM_TOTAL);
    lstm_c8_kernel<<<NCTA, THREADS, SMEM_TOTAL>>>(x, Wi, Wh, b, Wd, bd, out);
}